// round 1
// baseline (speedup 1.0000x reference)
#include <cuda_runtime.h>

// Problem constants
#define NNODE   10000
#define NEDGE   160000
#define FIN     3703
#define DMODEL  256
#define NHEAD   32
#define DK      16
#define QKV     512      // NHEAD*DK
#define NLAYER  7

// ---------------- device scratch (static allocations only) ----------------
__device__ float g_h   [NNODE * DMODEL];
__device__ float g_t0  [NNODE * DMODEL];
__device__ float g_t1  [NNODE * DMODEL];
__device__ float g_Q   [NNODE * QKV];
__device__ float g_Kb  [NNODE * QKV];
__device__ float g_Vb  [NNODE * QKV];
__device__ float g_attn[NNODE * QKV];

__device__ int g_cnt [NNODE];
__device__ int g_off [NNODE + 1];
__device__ int g_cur [NNODE];
__device__ int g_esrc[NEDGE];
__device__ int g_is64;

// ---------------- edge index dtype detection ----------------
// jnp.int64 under default JAX config may canonicalize to int32. Detect:
// int64 little-endian with values < 2^31 has zero high words at odd positions.
__global__ void detect_kernel(const unsigned int* __restrict__ w) {
    if (threadIdx.x == 0 && blockIdx.x == 0) {
        int is64 = 1;
        for (int i = 1; i < 128; i += 2) {
            if (w[i] != 0u) { is64 = 0; break; }
        }
        g_is64 = is64;
    }
}

__device__ __forceinline__ int read_edge(const void* eidx, int pos) {
    if (g_is64) return (int)(((const long long*)eidx)[pos]);
    return ((const int*)eidx)[pos];
}

// ---------------- CSR build ----------------
__global__ void zero_cnt_kernel() {
    int i = blockIdx.x * blockDim.x + threadIdx.x;
    if (i < NNODE) g_cnt[i] = 0;
}

__global__ void hist_kernel(const void* __restrict__ eidx) {
    int e = blockIdx.x * blockDim.x + threadIdx.x;
    if (e >= NEDGE) return;
    int d = read_edge(eidx, NEDGE + e);   // dst row
    atomicAdd(&g_cnt[d], 1);
}

__global__ void scan_kernel() {
    __shared__ int ss[1024];
    int t = threadIdx.x;
    const int CH = (NNODE + 1023) / 1024;
    int b = t * CH;
    int e = b + CH; if (e > NNODE) e = NNODE;
    int s = 0;
    for (int i = b; i < e && i < NNODE; i++) s += g_cnt[i];
    ss[t] = s;
    __syncthreads();
    for (int o = 1; o < 1024; o <<= 1) {
        int v = (t >= o) ? ss[t - o] : 0;
        __syncthreads();
        ss[t] += v;
        __syncthreads();
    }
    int base = ss[t] - s;  // exclusive prefix
    for (int i = b; i < e && i < NNODE; i++) {
        g_off[i] = base;
        g_cur[i] = base;
        base += g_cnt[i];
    }
    if (t == 1023) g_off[NNODE] = ss[1023];
}

__global__ void scatter_kernel(const void* __restrict__ eidx) {
    int e = blockIdx.x * blockDim.x + threadIdx.x;
    if (e >= NEDGE) return;
    int d = read_edge(eidx, NEDGE + e);
    int s = read_edge(eidx, e);
    int pos = atomicAdd(&g_cur[d], 1);
    g_esrc[pos] = s;
}

// ---------------- generic SGEMM: C = addend + bias + A @ B^T ----------------
// A: [M,K] row-major, B: [Nn,K] row-major, C: [M,Nn]. Nn multiple of 128.
__global__ __launch_bounds__(256, 2)
void sgemm_nt(const float* __restrict__ A, const float* __restrict__ B,
              const float* __restrict__ bias, const float* __restrict__ addend,
              float* __restrict__ C, int M, int Nn, int K)
{
    __shared__ float As[8][128];
    __shared__ float Bs[8][128];

    const int tid = threadIdx.x;
    const int tx = tid & 15;    // n direction (x8)
    const int ty = tid >> 4;    // m direction (x8)
    const int m0 = blockIdx.y * 128;
    const int n0 = blockIdx.x * 128;

    const int lr = tid >> 1;           // 0..127
    const int lc = (tid & 1) * 4;      // 0 or 4

    float acc[8][8];
#pragma unroll
    for (int i = 0; i < 8; i++)
#pragma unroll
        for (int j = 0; j < 8; j++) acc[i][j] = 0.f;

    const bool aValid = (m0 + lr) < M;
    const float* Ap = A + (size_t)(m0 + lr) * K;
    const float* Bp = B + (size_t)(n0 + lr) * K;

    for (int k0 = 0; k0 < K; k0 += 8) {
#pragma unroll
        for (int j = 0; j < 4; j++) {
            int k = k0 + lc + j;
            As[lc + j][lr] = (aValid && k < K) ? Ap[k] : 0.f;
            Bs[lc + j][lr] = (k < K) ? Bp[k] : 0.f;
        }
        __syncthreads();
#pragma unroll
        for (int kk = 0; kk < 8; kk++) {
            float4 a0 = *(const float4*)&As[kk][ty * 8];
            float4 a1 = *(const float4*)&As[kk][ty * 8 + 4];
            float4 b0 = *(const float4*)&Bs[kk][tx * 8];
            float4 b1 = *(const float4*)&Bs[kk][tx * 8 + 4];
            float ra[8] = {a0.x, a0.y, a0.z, a0.w, a1.x, a1.y, a1.z, a1.w};
            float rb[8] = {b0.x, b0.y, b0.z, b0.w, b1.x, b1.y, b1.z, b1.w};
#pragma unroll
            for (int i = 0; i < 8; i++)
#pragma unroll
                for (int j = 0; j < 8; j++) acc[i][j] += ra[i] * rb[j];
        }
        __syncthreads();
    }

#pragma unroll
    for (int i = 0; i < 8; i++) {
        int m = m0 + ty * 8 + i;
        if (m >= M) continue;
#pragma unroll
        for (int j = 0; j < 8; j++) {
            int n = n0 + tx * 8 + j;
            float v = acc[i][j];
            if (bias)   v += bias[n];
            if (addend) v += addend[(size_t)m * Nn + n];
            C[(size_t)m * Nn + n] = v;
        }
    }
}

// ---------------- LayerNorm: warp per row (D=256) ----------------
__global__ __launch_bounds__(256)
void ln_kernel(const float* __restrict__ X, const float* __restrict__ gamma,
               const float* __restrict__ beta, float* __restrict__ Y)
{
    int idx = blockIdx.x * blockDim.x + threadIdx.x;
    int row = idx >> 5;
    int lane = idx & 31;
    if (row >= NNODE) return;

    const float4* xp = (const float4*)(X + (size_t)row * DMODEL);
    float4 v0 = xp[lane];
    float4 v1 = xp[lane + 32];

    float s = v0.x + v0.y + v0.z + v0.w + v1.x + v1.y + v1.z + v1.w;
#pragma unroll
    for (int o = 16; o; o >>= 1) s += __shfl_xor_sync(0xffffffffu, s, o);
    float mean = s * (1.f / 256.f);

    float d, q = 0.f;
    d = v0.x - mean; q += d * d;  d = v0.y - mean; q += d * d;
    d = v0.z - mean; q += d * d;  d = v0.w - mean; q += d * d;
    d = v1.x - mean; q += d * d;  d = v1.y - mean; q += d * d;
    d = v1.z - mean; q += d * d;  d = v1.w - mean; q += d * d;
#pragma unroll
    for (int o = 16; o; o >>= 1) q += __shfl_xor_sync(0xffffffffu, q, o);
    float inv = rsqrtf(q * (1.f / 256.f) + 1e-5f);

    const float4* gp = (const float4*)gamma;
    const float4* bp = (const float4*)beta;
    float4 g0 = gp[lane], g1 = gp[lane + 32];
    float4 b0 = bp[lane], b1 = bp[lane + 32];

    float4 o0, o1;
    o0.x = (v0.x - mean) * inv * g0.x + b0.x;
    o0.y = (v0.y - mean) * inv * g0.y + b0.y;
    o0.z = (v0.z - mean) * inv * g0.z + b0.z;
    o0.w = (v0.w - mean) * inv * g0.w + b0.w;
    o1.x = (v1.x - mean) * inv * g1.x + b1.x;
    o1.y = (v1.y - mean) * inv * g1.y + b1.y;
    o1.z = (v1.z - mean) * inv * g1.z + b1.z;
    o1.w = (v1.w - mean) * inv * g1.w + b1.w;

    float4* yp = (float4*)(Y + (size_t)row * DMODEL);
    yp[lane] = o0;
    yp[lane + 32] = o1;
}

// ---------------- edge attention: warp per destination node ----------------
// Q,K,V row layout per node: [head][elem], 512 floats.
// alpha[a,b] = sum_h Q[dst][h][a]*K[src][h][b] / 4 ; softmax over b;
// partial[h] (per lane, over its 8 b's) accumulates over edges;
// final combine pairs lanes (a, half=0/1), write agg[n][h][a].
__global__ __launch_bounds__(128)
void attn_kernel(const float* __restrict__ Qm, const float* __restrict__ Km,
                 const float* __restrict__ Vm, float* __restrict__ Om)
{
    __shared__ float sm[4][3 * QKV];   // per warp: Q | K | V  (24 KB)

    const int gwarp = (blockIdx.x * blockDim.x + threadIdx.x) >> 5;
    const int lane  = threadIdx.x & 31;
    const int winb  = threadIdx.x >> 5;
    if (gwarp >= NNODE) return;

    const int i = gwarp;                 // destination node
    const int a = lane >> 1;             // alpha row 0..15
    const int half = lane & 1;           // b-half 0..1
    const int half2 = half * 2;

    float* Qs = &sm[winb][0];
    float* Ks = &sm[winb][QKV];
    float* Vs = &sm[winb][2 * QKV];
    const float4* Qs4 = (const float4*)Qs;  (void)Qs4;
    const float4* Ks4 = (const float4*)Ks;
    const float4* Vs4 = (const float4*)Vs;

    // load Q row (coalesced 4 x float4 per lane)
    {
        const float4* qg = (const float4*)(Qm + (size_t)i * QKV);
        float4* qd = (float4*)Qs;
#pragma unroll
        for (int v = 0; v < 4; v++) qd[lane + 32 * v] = qg[lane + 32 * v];
    }
    __syncwarp();

    float partial[32];
#pragma unroll
    for (int h = 0; h < 32; h++) partial[h] = 0.f;

    const int e0 = g_off[i];
    const int e1 = g_off[i + 1];

    for (int e = e0; e < e1; e++) {
        const int j = g_esrc[e];
        {
            const float4* kg = (const float4*)(Km + (size_t)j * QKV);
            const float4* vg = (const float4*)(Vm + (size_t)j * QKV);
            float4* kd = (float4*)Ks;
            float4* vd = (float4*)Vs;
#pragma unroll
            for (int v = 0; v < 4; v++) {
                kd[lane + 32 * v] = kg[lane + 32 * v];
                vd[lane + 32 * v] = vg[lane + 32 * v];
            }
        }
        __syncwarp();

        // alpha[a, b0..b0+7] = sum_h Q[h][a]*K[h][b]
        float acc[8];
#pragma unroll
        for (int b = 0; b < 8; b++) acc[b] = 0.f;
#pragma unroll
        for (int hh = 0; hh < 32; hh++) {
            float qa = Qs[hh * 16 + a];
            float4 k0 = Ks4[hh * 4 + half2];
            float4 k1 = Ks4[hh * 4 + half2 + 1];
            acc[0] += qa * k0.x; acc[1] += qa * k0.y;
            acc[2] += qa * k0.z; acc[3] += qa * k0.w;
            acc[4] += qa * k1.x; acc[5] += qa * k1.y;
            acc[6] += qa * k1.z; acc[7] += qa * k1.w;
        }
#pragma unroll
        for (int b = 0; b < 8; b++) acc[b] *= 0.25f;   // 1/sqrt(DK)

        // softmax over 16 b's (pairwise across half lanes)
        float mx = acc[0];
#pragma unroll
        for (int b = 1; b < 8; b++) mx = fmaxf(mx, acc[b]);
        mx = fmaxf(mx, __shfl_xor_sync(0xffffffffu, mx, 1));
        float ssum = 0.f;
#pragma unroll
        for (int b = 0; b < 8; b++) { acc[b] = __expf(acc[b] - mx); ssum += acc[b]; }
        ssum += __shfl_xor_sync(0xffffffffu, ssum, 1);
        float invs = 1.f / ssum;
#pragma unroll
        for (int b = 0; b < 8; b++) acc[b] *= invs;

        // msg partial: for each head, sum over my 8 b's of att*V[h][b]
#pragma unroll
        for (int hh = 0; hh < 32; hh++) {
            float4 v0 = Vs4[hh * 4 + half2];
            float4 v1 = Vs4[hh * 4 + half2 + 1];
            partial[hh] += acc[0] * v0.x + acc[1] * v0.y + acc[2] * v0.z + acc[3] * v0.w
                         + acc[4] * v1.x + acc[5] * v1.y + acc[6] * v1.z + acc[7] * v1.w;
        }
        __syncwarp();
    }

    // combine halves and write agg[i][h][a] (combined-heads layout h*16+a)
    float* op = Om + (size_t)i * QKV;
#pragma unroll
    for (int h = 0; h < 32; h++) {
        float tot = partial[h] + __shfl_xor_sync(0xffffffffu, partial[h], 1);
        if ((h >> 4) == half) op[h * 16 + a] = tot;
    }
}

// ---------------- host launcher ----------------
extern "C" void kernel_launch(void* const* d_in, const int* in_sizes, int n_in,
                              void* d_out, int out_size)
{
    const float* x       = (const float*)d_in[0];
    const void*  eidx    =               d_in[1];
    const float* W_embed = (const float*)d_in[2];
    const float* Wq      = (const float*)d_in[3];
    const float* Wk      = (const float*)d_in[4];
    const float* Wv      = (const float*)d_in[5];
    const float* Wo      = (const float*)d_in[6];
    const float* bo      = (const float*)d_in[7];
    const float* Wm      = (const float*)d_in[8];
    const float* bm      = (const float*)d_in[9];
    const float* g_ln    = (const float*)d_in[10];
    const float* b_ln    = (const float*)d_in[11];
    const float* g_mlp   = (const float*)d_in[12];
    const float* b_mlp   = (const float*)d_in[13];
    float* out = (float*)d_out;

    float *ph, *pt0, *pt1, *pQ, *pK, *pV, *pA;
    cudaGetSymbolAddress((void**)&ph,  g_h);
    cudaGetSymbolAddress((void**)&pt0, g_t0);
    cudaGetSymbolAddress((void**)&pt1, g_t1);
    cudaGetSymbolAddress((void**)&pQ,  g_Q);
    cudaGetSymbolAddress((void**)&pK,  g_Kb);
    cudaGetSymbolAddress((void**)&pV,  g_Vb);
    cudaGetSymbolAddress((void**)&pA,  g_attn);

    // ---- build CSR by destination (once per launch; inputs fixed) ----
    detect_kernel<<<1, 32>>>((const unsigned int*)eidx);
    zero_cnt_kernel<<<(NNODE + 255) / 256, 256>>>();
    hist_kernel<<<(NEDGE + 255) / 256, 256>>>(eidx);
    scan_kernel<<<1, 1024>>>();
    scatter_kernel<<<(NEDGE + 255) / 256, 256>>>(eidx);

    const dim3 gEmb(DMODEL / 128, (NNODE + 127) / 128);      // 2 x 79
    const dim3 gQKV(QKV / 128,    (NNODE + 127) / 128);      // 4 x 79
    const dim3 gD  (DMODEL / 128, (NNODE + 127) / 128);      // 2 x 79

    // ---- embedding ----
    sgemm_nt<<<gEmb, 256>>>(x, W_embed, nullptr, nullptr, ph, NNODE, DMODEL, FIN);

    // ---- encoder layers ----
    for (int l = 0; l < NLAYER; l++) {
        const float* wq = Wq + (size_t)l * QKV * DMODEL;
        const float* wk = Wk + (size_t)l * QKV * DMODEL;
        const float* wv = Wv + (size_t)l * QKV * DMODEL;
        const float* wo = Wo + (size_t)l * DMODEL * QKV;
        const float* wm = Wm + (size_t)l * DMODEL * DMODEL;

        sgemm_nt<<<gQKV, 256>>>(ph, wq, nullptr, nullptr, pQ, NNODE, QKV, DMODEL);
        sgemm_nt<<<gQKV, 256>>>(ph, wk, nullptr, nullptr, pK, NNODE, QKV, DMODEL);
        sgemm_nt<<<gQKV, 256>>>(ph, wv, nullptr, nullptr, pV, NNODE, QKV, DMODEL);

        attn_kernel<<<(NNODE + 3) / 4, 128>>>(pQ, pK, pV, pA);

        // h1x = h + attn @ Wo^T + bo ; h1 = LN(h1x)
        sgemm_nt<<<gD, 256>>>(pA, wo, bo + (size_t)l * DMODEL, ph, pt0,
                              NNODE, DMODEL, QKV);
        ln_kernel<<<(NNODE * 32 + 255) / 256, 256>>>(pt0, g_ln + (size_t)l * DMODEL,
                                                     b_ln + (size_t)l * DMODEL, pt1);

        // h2 = h1 + h1 @ Wm^T + bm ; h = LN(h2)
        sgemm_nt<<<gD, 256>>>(pt1, wm, bm + (size_t)l * DMODEL, pt1, pt0,
                              NNODE, DMODEL, DMODEL);
        ln_kernel<<<(NNODE * 32 + 255) / 256, 256>>>(pt0, g_mlp + (size_t)l * DMODEL,
                                                     b_mlp + (size_t)l * DMODEL,
                                                     (l == NLAYER - 1) ? out : ph);
    }
}

// round 2
// speedup vs baseline: 1.3782x; 1.3782x over previous
#include <cuda_runtime.h>

// Problem constants
#define NNODE   10000
#define NEDGE   160000
#define FIN     3703
#define DMODEL  256
#define NHEAD   32
#define DK      16
#define QKV     512      // NHEAD*DK
#define NLAYER  7

// GEMM tiling
#define BM 128
#define BN 128
#define BK 16
#define KSTRIDE 20                 // BK + 4 pad (bank-conflict-free: 20 mod 32)
#define ATILE (128*KSTRIDE)        // floats per operand tile
#define SSZ   (4*ATILE)            // per-stage floats (A_hi A_lo B_hi B_lo)
#define GEMM_SMEM_BYTES (2*SSZ*4)  // 81920 bytes, double buffered

// ---------------- device scratch (static allocations only) ----------------
__device__ float g_h   [NNODE * DMODEL];
__device__ float g_t0  [NNODE * DMODEL];
__device__ float g_t1  [NNODE * DMODEL];
__device__ float g_Q   [NNODE * QKV];
__device__ float g_Kb  [NNODE * QKV];
__device__ float g_Vb  [NNODE * QKV];
__device__ float g_attn[NNODE * QKV];

__device__ int g_cnt [NNODE];
__device__ int g_off [NNODE + 1];
__device__ int g_cur [NNODE];
__device__ int g_esrc[NEDGE];
__device__ int g_is64;

// ---------------- edge index dtype detection ----------------
__global__ void detect_kernel(const unsigned int* __restrict__ w) {
    if (threadIdx.x == 0 && blockIdx.x == 0) {
        int is64 = 1;
        for (int i = 1; i < 128; i += 2) {
            if (w[i] != 0u) { is64 = 0; break; }
        }
        g_is64 = is64;
    }
}

__device__ __forceinline__ int read_edge(const void* eidx, int pos) {
    if (g_is64) return (int)(((const long long*)eidx)[pos]);
    return ((const int*)eidx)[pos];
}

// ---------------- CSR build ----------------
__global__ void zero_cnt_kernel() {
    int i = blockIdx.x * blockDim.x + threadIdx.x;
    if (i < NNODE) g_cnt[i] = 0;
}

__global__ void hist_kernel(const void* __restrict__ eidx) {
    int e = blockIdx.x * blockDim.x + threadIdx.x;
    if (e >= NEDGE) return;
    int d = read_edge(eidx, NEDGE + e);
    atomicAdd(&g_cnt[d], 1);
}

__global__ void scan_kernel() {
    __shared__ int ss[1024];
    int t = threadIdx.x;
    const int CH = (NNODE + 1023) / 1024;
    int b = t * CH;
    int e = b + CH; if (e > NNODE) e = NNODE;
    int s = 0;
    for (int i = b; i < e && i < NNODE; i++) s += g_cnt[i];
    ss[t] = s;
    __syncthreads();
    for (int o = 1; o < 1024; o <<= 1) {
        int v = (t >= o) ? ss[t - o] : 0;
        __syncthreads();
        ss[t] += v;
        __syncthreads();
    }
    int base = ss[t] - s;
    for (int i = b; i < e && i < NNODE; i++) {
        g_off[i] = base;
        g_cur[i] = base;
        base += g_cnt[i];
    }
    if (t == 1023) g_off[NNODE] = ss[1023];
}

__global__ void scatter_kernel(const void* __restrict__ eidx) {
    int e = blockIdx.x * blockDim.x + threadIdx.x;
    if (e >= NEDGE) return;
    int d = read_edge(eidx, NEDGE + e);
    int s = read_edge(eidx, e);
    int pos = atomicAdd(&g_cur[d], 1);
    g_esrc[pos] = s;
}

// ---------------- TF32 helpers ----------------
__device__ __forceinline__ void split_store(float* hi, float* lo, int idx, float x) {
    unsigned h;
    asm("cvt.rna.tf32.f32 %0, %1;" : "=r"(h) : "f"(x));
    float hf = __uint_as_float(h);
    float r = x - hf;
    unsigned l;
    asm("cvt.rna.tf32.f32 %0, %1;" : "=r"(l) : "f"(r));
    hi[idx] = hf;
    lo[idx] = __uint_as_float(l);
}

__device__ __forceinline__ void mma8(float* c,
                                     float a0, float a1, float a2, float a3,
                                     float b0, float b1) {
    asm volatile(
        "mma.sync.aligned.m16n8k8.row.col.f32.tf32.tf32.f32 "
        "{%0,%1,%2,%3}, {%4,%5,%6,%7}, {%8,%9}, {%0,%1,%2,%3};\n"
        : "+f"(c[0]), "+f"(c[1]), "+f"(c[2]), "+f"(c[3])
        : "r"(__float_as_uint(a0)), "r"(__float_as_uint(a1)),
          "r"(__float_as_uint(a2)), "r"(__float_as_uint(a3)),
          "r"(__float_as_uint(b0)), "r"(__float_as_uint(b1)));
}

__device__ __forceinline__ float4 ldg4_guard(const float* __restrict__ p, int K,
                                             int row, int valid_row, int kbase) {
    float4 v = make_float4(0.f, 0.f, 0.f, 0.f);
    if (!valid_row) return v;
    const float* q = p + (size_t)row * K + kbase;
    if ((K & 3) == 0) {
        // all K%4==0 cases here are multiples of BK, so tile is always full
        v = *(const float4*)q;
    } else {
        if (kbase + 4 <= K) { v.x = q[0]; v.y = q[1]; v.z = q[2]; v.w = q[3]; }
        else {
            if (kbase     < K) v.x = q[0];
            if (kbase + 1 < K) v.y = q[1];
            if (kbase + 2 < K) v.z = q[2];
            if (kbase + 3 < K) v.w = q[3];
        }
    }
    return v;
}

// ---------------- GEMM: C = addend + bias + A @ B^T  (3xTF32 tensor cores) ----
// A: [M,K] row-major, B: [Nn,K] row-major, C: [M,Nn]. Nn multiple of 128.
__global__ __launch_bounds__(256, 1)
void gemm_tf32(const float* __restrict__ A, const float* __restrict__ B,
               const float* __restrict__ bias, const float* __restrict__ addend,
               float* __restrict__ C, int M, int Nn, int K)
{
    extern __shared__ float smem[];

    const int tid = threadIdx.x;
    const int m0 = blockIdx.y * BM;
    const int n0 = blockIdx.x * BN;

    const int lane = tid & 31;
    const int wid  = tid >> 5;
    const int wm = wid & 1;        // 2 warps over M (64 rows each)
    const int wn = wid >> 1;       // 4 warps over N (32 cols each)
    const int g  = lane >> 2;      // 0..7
    const int tg = lane & 3;       // 0..3

    float acc[4][4][4];
#pragma unroll
    for (int i = 0; i < 4; i++)
#pragma unroll
        for (int j = 0; j < 4; j++)
#pragma unroll
            for (int q = 0; q < 4; q++) acc[i][j][q] = 0.f;

    const int nkt = (K + BK - 1) / BK;

    float4 ra[2], rb[2];

    // prologue: fetch + stage tile 0
#pragma unroll
    for (int j = 0; j < 2; j++) {
        int q = tid * 2 + j, row = q >> 2, kk = (q & 3) * 4, kbase = kk;
        ra[j] = ldg4_guard(A, K, m0 + row, (m0 + row) < M, kbase);
        rb[j] = ldg4_guard(B, K, n0 + row, 1, kbase);
    }
    {
        float* sAh = smem;
        float* sAl = sAh + ATILE;
        float* sBh = sAl + ATILE;
        float* sBl = sBh + ATILE;
#pragma unroll
        for (int j = 0; j < 2; j++) {
            int q = tid * 2 + j, row = q >> 2, kk = (q & 3) * 4;
            int base = row * KSTRIDE + kk;
            split_store(sAh, sAl, base + 0, ra[j].x);
            split_store(sAh, sAl, base + 1, ra[j].y);
            split_store(sAh, sAl, base + 2, ra[j].z);
            split_store(sAh, sAl, base + 3, ra[j].w);
            split_store(sBh, sBl, base + 0, rb[j].x);
            split_store(sBh, sBl, base + 1, rb[j].y);
            split_store(sBh, sBl, base + 2, rb[j].z);
            split_store(sBh, sBl, base + 3, rb[j].w);
        }
    }
    __syncthreads();

    for (int kt = 0; kt < nkt; kt++) {
        const int cur = kt & 1;

        if (kt + 1 < nkt) {
#pragma unroll
            for (int j = 0; j < 2; j++) {
                int q = tid * 2 + j, row = q >> 2, kk = (q & 3) * 4;
                int kbase = (kt + 1) * BK + kk;
                ra[j] = ldg4_guard(A, K, m0 + row, (m0 + row) < M, kbase);
                rb[j] = ldg4_guard(B, K, n0 + row, 1, kbase);
            }
        }

        // compute on stage cur
        {
            float* sAh = smem + cur * SSZ;
            float* sAl = sAh + ATILE;
            float* sBh = sAl + ATILE;
            float* sBl = sBh + ATILE;

#pragma unroll
            for (int ks = 0; ks < 2; ks++) {
                const int kb = ks * 8;
                float bh[4][2], bl[4][2];
#pragma unroll
                for (int j = 0; j < 4; j++) {
                    int rbase = (wn * 32 + j * 8 + g) * KSTRIDE + kb + tg;
                    bh[j][0] = sBh[rbase];     bh[j][1] = sBh[rbase + 4];
                    bl[j][0] = sBl[rbase];     bl[j][1] = sBl[rbase + 4];
                }
#pragma unroll
                for (int i = 0; i < 4; i++) {
                    int rbase = (wm * 64 + i * 16 + g) * KSTRIDE + kb + tg;
                    float ah0 = sAh[rbase];
                    float ah1 = sAh[rbase + 8 * KSTRIDE];
                    float ah2 = sAh[rbase + 4];
                    float ah3 = sAh[rbase + 8 * KSTRIDE + 4];
                    float al0 = sAl[rbase];
                    float al1 = sAl[rbase + 8 * KSTRIDE];
                    float al2 = sAl[rbase + 4];
                    float al3 = sAl[rbase + 8 * KSTRIDE + 4];
#pragma unroll
                    for (int j = 0; j < 4; j++) {
                        mma8(acc[i][j], ah0, ah1, ah2, ah3, bh[j][0], bh[j][1]);
                        mma8(acc[i][j], al0, al1, al2, al3, bh[j][0], bh[j][1]);
                        mma8(acc[i][j], ah0, ah1, ah2, ah3, bl[j][0], bl[j][1]);
                    }
                }
            }
        }

        if (kt + 1 < nkt) {
            float* sAh = smem + ((kt + 1) & 1) * SSZ;
            float* sAl = sAh + ATILE;
            float* sBh = sAl + ATILE;
            float* sBl = sBh + ATILE;
#pragma unroll
            for (int j = 0; j < 2; j++) {
                int q = tid * 2 + j, row = q >> 2, kk = (q & 3) * 4;
                int base = row * KSTRIDE + kk;
                split_store(sAh, sAl, base + 0, ra[j].x);
                split_store(sAh, sAl, base + 1, ra[j].y);
                split_store(sAh, sAl, base + 2, ra[j].z);
                split_store(sAh, sAl, base + 3, ra[j].w);
                split_store(sBh, sBl, base + 0, rb[j].x);
                split_store(sBh, sBl, base + 1, rb[j].y);
                split_store(sBh, sBl, base + 2, rb[j].z);
                split_store(sBh, sBl, base + 3, rb[j].w);
            }
        }
        __syncthreads();
    }

    // epilogue
#pragma unroll
    for (int i = 0; i < 4; i++) {
        int mrow = m0 + wm * 64 + i * 16 + g;
#pragma unroll
        for (int j = 0; j < 4; j++) {
            int ncol = n0 + wn * 32 + j * 8 + tg * 2;
            float bv0 = 0.f, bv1 = 0.f;
            if (bias) { bv0 = bias[ncol]; bv1 = bias[ncol + 1]; }
            if (mrow < M) {
                float v0 = acc[i][j][0] + bv0;
                float v1 = acc[i][j][1] + bv1;
                if (addend) {
                    v0 += addend[(size_t)mrow * Nn + ncol];
                    v1 += addend[(size_t)mrow * Nn + ncol + 1];
                }
                C[(size_t)mrow * Nn + ncol]     = v0;
                C[(size_t)mrow * Nn + ncol + 1] = v1;
            }
            if (mrow + 8 < M) {
                float v2 = acc[i][j][2] + bv0;
                float v3 = acc[i][j][3] + bv1;
                if (addend) {
                    v2 += addend[(size_t)(mrow + 8) * Nn + ncol];
                    v3 += addend[(size_t)(mrow + 8) * Nn + ncol + 1];
                }
                C[(size_t)(mrow + 8) * Nn + ncol]     = v2;
                C[(size_t)(mrow + 8) * Nn + ncol + 1] = v3;
            }
        }
    }
}

// ---------------- LayerNorm: warp per row (D=256) ----------------
__global__ __launch_bounds__(256)
void ln_kernel(const float* __restrict__ X, const float* __restrict__ gamma,
               const float* __restrict__ beta, float* __restrict__ Y)
{
    int idx = blockIdx.x * blockDim.x + threadIdx.x;
    int row = idx >> 5;
    int lane = idx & 31;
    if (row >= NNODE) return;

    const float4* xp = (const float4*)(X + (size_t)row * DMODEL);
    float4 v0 = xp[lane];
    float4 v1 = xp[lane + 32];

    float s = v0.x + v0.y + v0.z + v0.w + v1.x + v1.y + v1.z + v1.w;
#pragma unroll
    for (int o = 16; o; o >>= 1) s += __shfl_xor_sync(0xffffffffu, s, o);
    float mean = s * (1.f / 256.f);

    float d, q = 0.f;
    d = v0.x - mean; q += d * d;  d = v0.y - mean; q += d * d;
    d = v0.z - mean; q += d * d;  d = v0.w - mean; q += d * d;
    d = v1.x - mean; q += d * d;  d = v1.y - mean; q += d * d;
    d = v1.z - mean; q += d * d;  d = v1.w - mean; q += d * d;
#pragma unroll
    for (int o = 16; o; o >>= 1) q += __shfl_xor_sync(0xffffffffu, q, o);
    float inv = rsqrtf(q * (1.f / 256.f) + 1e-5f);

    const float4* gp = (const float4*)gamma;
    const float4* bp = (const float4*)beta;
    float4 g0 = gp[lane], g1 = gp[lane + 32];
    float4 b0 = bp[lane], b1 = bp[lane + 32];

    float4 o0, o1;
    o0.x = (v0.x - mean) * inv * g0.x + b0.x;
    o0.y = (v0.y - mean) * inv * g0.y + b0.y;
    o0.z = (v0.z - mean) * inv * g0.z + b0.z;
    o0.w = (v0.w - mean) * inv * g0.w + b0.w;
    o1.x = (v1.x - mean) * inv * g1.x + b1.x;
    o1.y = (v1.y - mean) * inv * g1.y + b1.y;
    o1.z = (v1.z - mean) * inv * g1.z + b1.z;
    o1.w = (v1.w - mean) * inv * g1.w + b1.w;

    float4* yp = (float4*)(Y + (size_t)row * DMODEL);
    yp[lane] = o0;
    yp[lane + 32] = o1;
}

// ---------------- edge attention: warp per destination node ----------------
__global__ __launch_bounds__(128)
void attn_kernel(const float* __restrict__ Qm, const float* __restrict__ Km,
                 const float* __restrict__ Vm, float* __restrict__ Om)
{
    __shared__ float sm[4][3 * QKV];

    const int gwarp = (blockIdx.x * blockDim.x + threadIdx.x) >> 5;
    const int lane  = threadIdx.x & 31;
    const int winb  = threadIdx.x >> 5;
    if (gwarp >= NNODE) return;

    const int i = gwarp;
    const int a = lane >> 1;
    const int half = lane & 1;
    const int half2 = half * 2;

    float* Qs = &sm[winb][0];
    float* Ks = &sm[winb][QKV];
    float* Vs = &sm[winb][2 * QKV];
    const float4* Ks4 = (const float4*)Ks;
    const float4* Vs4 = (const float4*)Vs;

    {
        const float4* qg = (const float4*)(Qm + (size_t)i * QKV);
        float4* qd = (float4*)Qs;
#pragma unroll
        for (int v = 0; v < 4; v++) qd[lane + 32 * v] = qg[lane + 32 * v];
    }
    __syncwarp();

    float partial[32];
#pragma unroll
    for (int h = 0; h < 32; h++) partial[h] = 0.f;

    const int e0 = g_off[i];
    const int e1 = g_off[i + 1];

    for (int e = e0; e < e1; e++) {
        const int j = g_esrc[e];
        {
            const float4* kg = (const float4*)(Km + (size_t)j * QKV);
            const float4* vg = (const float4*)(Vm + (size_t)j * QKV);
            float4* kd = (float4*)Ks;
            float4* vd = (float4*)Vs;
#pragma unroll
            for (int v = 0; v < 4; v++) {
                kd[lane + 32 * v] = kg[lane + 32 * v];
                vd[lane + 32 * v] = vg[lane + 32 * v];
            }
        }
        __syncwarp();

        float acc[8];
#pragma unroll
        for (int b = 0; b < 8; b++) acc[b] = 0.f;
#pragma unroll
        for (int hh = 0; hh < 32; hh++) {
            float qa = Qs[hh * 16 + a];
            float4 k0 = Ks4[hh * 4 + half2];
            float4 k1 = Ks4[hh * 4 + half2 + 1];
            acc[0] += qa * k0.x; acc[1] += qa * k0.y;
            acc[2] += qa * k0.z; acc[3] += qa * k0.w;
            acc[4] += qa * k1.x; acc[5] += qa * k1.y;
            acc[6] += qa * k1.z; acc[7] += qa * k1.w;
        }
#pragma unroll
        for (int b = 0; b < 8; b++) acc[b] *= 0.25f;

        float mx = acc[0];
#pragma unroll
        for (int b = 1; b < 8; b++) mx = fmaxf(mx, acc[b]);
        mx = fmaxf(mx, __shfl_xor_sync(0xffffffffu, mx, 1));
        float ssum = 0.f;
#pragma unroll
        for (int b = 0; b < 8; b++) { acc[b] = __expf(acc[b] - mx); ssum += acc[b]; }
        ssum += __shfl_xor_sync(0xffffffffu, ssum, 1);
        float invs = 1.f / ssum;
#pragma unroll
        for (int b = 0; b < 8; b++) acc[b] *= invs;

#pragma unroll
        for (int hh = 0; hh < 32; hh++) {
            float4 v0 = Vs4[hh * 4 + half2];
            float4 v1 = Vs4[hh * 4 + half2 + 1];
            partial[hh] += acc[0] * v0.x + acc[1] * v0.y + acc[2] * v0.z + acc[3] * v0.w
                         + acc[4] * v1.x + acc[5] * v1.y + acc[6] * v1.z + acc[7] * v1.w;
        }
        __syncwarp();
    }

    float* op = Om + (size_t)i * QKV;
#pragma unroll
    for (int h = 0; h < 32; h++) {
        float tot = partial[h] + __shfl_xor_sync(0xffffffffu, partial[h], 1);
        if ((h >> 4) == half) op[h * 16 + a] = tot;
    }
}

// ---------------- host launcher ----------------
extern "C" void kernel_launch(void* const* d_in, const int* in_sizes, int n_in,
                              void* d_out, int out_size)
{
    const float* x       = (const float*)d_in[0];
    const void*  eidx    =               d_in[1];
    const float* W_embed = (const float*)d_in[2];
    const float* Wq      = (const float*)d_in[3];
    const float* Wk      = (const float*)d_in[4];
    const float* Wv      = (const float*)d_in[5];
    const float* Wo      = (const float*)d_in[6];
    const float* bo      = (const float*)d_in[7];
    const float* Wm      = (const float*)d_in[8];
    const float* bm      = (const float*)d_in[9];
    const float* g_ln    = (const float*)d_in[10];
    const float* b_ln    = (const float*)d_in[11];
    const float* g_mlp   = (const float*)d_in[12];
    const float* b_mlp   = (const float*)d_in[13];
    float* out = (float*)d_out;

    float *ph, *pt0, *pt1, *pQ, *pK, *pV, *pA;
    cudaGetSymbolAddress((void**)&ph,  g_h);
    cudaGetSymbolAddress((void**)&pt0, g_t0);
    cudaGetSymbolAddress((void**)&pt1, g_t1);
    cudaGetSymbolAddress((void**)&pQ,  g_Q);
    cudaGetSymbolAddress((void**)&pK,  g_Kb);
    cudaGetSymbolAddress((void**)&pV,  g_Vb);
    cudaGetSymbolAddress((void**)&pA,  g_attn);

    cudaFuncSetAttribute(gemm_tf32, cudaFuncAttributeMaxDynamicSharedMemorySize,
                         GEMM_SMEM_BYTES);

    const dim3 gEmb(DMODEL / BN, (NNODE + BM - 1) / BM);
    const dim3 gQKV(QKV / BN,    (NNODE + BM - 1) / BM);
    const dim3 gD  (DMODEL / BN, (NNODE + BM - 1) / BM);

    // ---- embedding + layer-0 QKV first (lands a GEMM in the ncu slot) ----
    gemm_tf32<<<gEmb, 256, GEMM_SMEM_BYTES>>>(x, W_embed, nullptr, nullptr, ph,
                                              NNODE, DMODEL, FIN);
    gemm_tf32<<<gQKV, 256, GEMM_SMEM_BYTES>>>(ph, Wq, nullptr, nullptr, pQ,
                                              NNODE, QKV, DMODEL);
    gemm_tf32<<<gQKV, 256, GEMM_SMEM_BYTES>>>(ph, Wk, nullptr, nullptr, pK,
                                              NNODE, QKV, DMODEL);
    gemm_tf32<<<gQKV, 256, GEMM_SMEM_BYTES>>>(ph, Wv, nullptr, nullptr, pV,
                                              NNODE, QKV, DMODEL);

    // ---- CSR build (needed only before the first attention) ----
    detect_kernel<<<1, 32>>>((const unsigned int*)eidx);
    zero_cnt_kernel<<<(NNODE + 255) / 256, 256>>>();
    hist_kernel<<<(NEDGE + 255) / 256, 256>>>(eidx);
    scan_kernel<<<1, 1024>>>();
    scatter_kernel<<<(NEDGE + 255) / 256, 256>>>(eidx);

    // ---- encoder layers ----
    for (int l = 0; l < NLAYER; l++) {
        const float* wq = Wq + (size_t)l * QKV * DMODEL;
        const float* wk = Wk + (size_t)l * QKV * DMODEL;
        const float* wv = Wv + (size_t)l * QKV * DMODEL;
        const float* wo = Wo + (size_t)l * DMODEL * QKV;
        const float* wm = Wm + (size_t)l * DMODEL * DMODEL;

        if (l > 0) {
            gemm_tf32<<<gQKV, 256, GEMM_SMEM_BYTES>>>(ph, wq, nullptr, nullptr, pQ,
                                                      NNODE, QKV, DMODEL);
            gemm_tf32<<<gQKV, 256, GEMM_SMEM_BYTES>>>(ph, wk, nullptr, nullptr, pK,
                                                      NNODE, QKV, DMODEL);
            gemm_tf32<<<gQKV, 256, GEMM_SMEM_BYTES>>>(ph, wv, nullptr, nullptr, pV,
                                                      NNODE, QKV, DMODEL);
        }

        attn_kernel<<<(NNODE + 3) / 4, 128>>>(pQ, pK, pV, pA);

        // h1x = h + attn @ Wo^T + bo ; h1 = LN(h1x)
        gemm_tf32<<<gD, 256, GEMM_SMEM_BYTES>>>(pA, wo, bo + (size_t)l * DMODEL, ph,
                                                pt0, NNODE, DMODEL, QKV);
        ln_kernel<<<(NNODE * 32 + 255) / 256, 256>>>(pt0, g_ln + (size_t)l * DMODEL,
                                                     b_ln + (size_t)l * DMODEL, pt1);

        // h2 = h1 + h1 @ Wm^T + bm ; h = LN(h2)
        gemm_tf32<<<gD, 256, GEMM_SMEM_BYTES>>>(pt1, wm, bm + (size_t)l * DMODEL,
                                                pt1, pt0, NNODE, DMODEL, DMODEL);
        ln_kernel<<<(NNODE * 32 + 255) / 256, 256>>>(pt0, g_mlp + (size_t)l * DMODEL,
                                                     b_mlp + (size_t)l * DMODEL,
                                                     (l == NLAYER - 1) ? out : ph);
    }
}